// round 8
// baseline (speedup 1.0000x reference)
#include <cuda_runtime.h>

// DigitCaps broadcasted batched matvec:
//   u_hat[b,r,c,o] = sum_i W[r,c,o,i] * x[b,r,i] + bias[o]
// B=512, R=1152, C=10, O=16, I=8, fp32.
//
// R6: BT 16 -> 32. R5 was L1-bound (84%) with W LDS.128 the dominant term
// (2B of W through the smem crossbar per 1B of output; LDS.128 = 4 crossbar
// cycles/warp-instr). Doubling the batch tile halves W-LDS cycles per output:
// per warp-cp now W 32 + x 32 + STG 32 = 96 cyc covering 32 outputs/thread.
// Everything else unchanged from R5: RB=4, block 128, padded conflict-free
// smem W rows, broadcast x LDS, 4-wavefront coalesced __stcs stores.
// Lane = bg(4) x c2(2) x o4(4). Each thread: 8 b's (k) x 2 c's x 4 o's.

#define DC_B 512
#define DC_R 1152
#define DC_C 10
#define DC_O 16
#define DC_I 8

#define RB 4     // r rows per block (one per warp)
#define BT 32    // batch elems per block
// smem W: 4r * 10c * 4(o4) rows of 36 floats = 5760 floats (23KB)
// smem x: 32 b * 36 floats (32 data + 4 pad)  = 1152 floats (4.6KB)
#define SW_FLOATS 5760
#define SX_FLOATS 1152
#define SMEM_BYTES ((SW_FLOATS + SX_FLOATS) * 4)

__global__ __launch_bounds__(128, 7)
void digitcaps_kernel(const float* __restrict__ x,
                      const float* __restrict__ W,
                      const float* __restrict__ bias,
                      float* __restrict__ out)
{
    extern __shared__ float smem[];
    float* sW = smem;                 // [g][36], g = (r_local*10 + c)*4 + o4
    float* sx = smem + SW_FLOATS;     // [b_local][36]: 4 r * 8 i + pad

    const int tid = threadIdx.x;
    const int r0  = blockIdx.x * RB;
    const int b0  = blockIdx.y * BT;

    // ---- cooperative W load: 4 r rows * 1280 floats = 1280 float4, coalesced ----
    {
        const float4* Wg = reinterpret_cast<const float4*>(W + (size_t)r0 * (DC_C * DC_O * DC_I));
#pragma unroll
        for (int q4 = 0; q4 < 10; ++q4) {
            const int q = q4 * 128 + tid;           // float4 index in W tile
            const float4 v = Wg[q];
            // q -> (rc, o, ih): flat = ((rc)*16 + o)*2 + ih
            const int ih = q & 1;
            const int o  = (q >> 1) & 15;
            const int rc = q >> 5;                   // r_local*10 + c
            const int g  = rc * 4 + (o >> 2);
            *reinterpret_cast<float4*>(sW + g * 36 + (o & 3) * 8 + ih * 4) = v;
        }
    }
    // ---- cooperative x load: 32 b * 32 floats = 256 float4 (2 per thread),
    //      each b = exactly one 128B line of x ----
    {
#pragma unroll
        for (int it = 0; it < 2; ++it) {
            const int b_i = (tid >> 3) + it * 16;    // 0..31
            const int m   = tid & 7;                 // float4 index within line
            const float4 v = *reinterpret_cast<const float4*>(
                x + ((size_t)(b0 + b_i) * DC_R + r0) * DC_I + m * 4);
            *reinterpret_cast<float4*>(sx + b_i * 36 + m * 4) = v;
        }
    }
    __syncthreads();

    const int lane = tid & 31;
    const int w    = tid >> 5;       // warp id == r_local (0..3)
    const int bg   = lane >> 3;      // 0..3 batch group
    const int c2   = (lane >> 2) & 1;
    const int o4   = lane & 3;

    const int r = r0 + w;

    const float4 bb = *reinterpret_cast<const float4*>(bias + o4 * 4);

    // out element offset: ((b*R + r)*C + c)*O + o
    const size_t out_r = (size_t)r * (DC_C * DC_O);

#pragma unroll
    for (int cp = 0; cp < 5; ++cp) {
        const int c = cp * 2 + c2;
        // W row for (r, c, o4): 32 floats = 4 o * 8 i. 8 distinct rows per warp,
        // row stride 36 floats -> conflict-free bank groups.
        const float* wr = sW + ((w * DC_C + c) * 4 + o4) * 36;
        const float4 w0a = *reinterpret_cast<const float4*>(wr + 0);
        const float4 w0b = *reinterpret_cast<const float4*>(wr + 4);
        const float4 w1a = *reinterpret_cast<const float4*>(wr + 8);
        const float4 w1b = *reinterpret_cast<const float4*>(wr + 12);
        const float4 w2a = *reinterpret_cast<const float4*>(wr + 16);
        const float4 w2b = *reinterpret_cast<const float4*>(wr + 20);
        const float4 w3a = *reinterpret_cast<const float4*>(wr + 24);
        const float4 w3b = *reinterpret_cast<const float4*>(wr + 28);

#pragma unroll
        for (int k = 0; k < 8; ++k) {
            const int bl = k * 4 + bg;
            // broadcast LDS: 4 distinct 16B addrs per warp instr
            const float4 va = *reinterpret_cast<const float4*>(sx + bl * 36 + w * 8);
            const float4 vb = *reinterpret_cast<const float4*>(sx + bl * 36 + w * 8 + 4);

            float4 acc;
            acc.x = fmaf(w0a.x, va.x, fmaf(w0a.y, va.y,
                    fmaf(w0a.z, va.z, fmaf(w0a.w, va.w,
                    fmaf(w0b.x, vb.x, fmaf(w0b.y, vb.y,
                    fmaf(w0b.z, vb.z, fmaf(w0b.w, vb.w, bb.x))))))));
            acc.y = fmaf(w1a.x, va.x, fmaf(w1a.y, va.y,
                    fmaf(w1a.z, va.z, fmaf(w1a.w, va.w,
                    fmaf(w1b.x, vb.x, fmaf(w1b.y, vb.y,
                    fmaf(w1b.z, vb.z, fmaf(w1b.w, vb.w, bb.y))))))));
            acc.z = fmaf(w2a.x, va.x, fmaf(w2a.y, va.y,
                    fmaf(w2a.z, va.z, fmaf(w2a.w, va.w,
                    fmaf(w2b.x, vb.x, fmaf(w2b.y, vb.y,
                    fmaf(w2b.z, vb.z, fmaf(w2b.w, vb.w, bb.z))))))));
            acc.w = fmaf(w3a.x, va.x, fmaf(w3a.y, va.y,
                    fmaf(w3a.z, va.z, fmaf(w3a.w, va.w,
                    fmaf(w3b.x, vb.x, fmaf(w3b.y, vb.y,
                    fmaf(w3b.z, vb.z, fmaf(w3b.w, vb.w, bb.w))))))));

            const int b = b0 + bl;
            // Per STG warp instr: 4 x 128B contiguous segments -> 4 wavefronts.
            float4* op = reinterpret_cast<float4*>(
                out + (size_t)b * (DC_R * DC_C * DC_O) + out_r
                    + (size_t)c * DC_O + o4 * 4);
            __stcs(op, acc);
        }
    }
}

extern "C" void kernel_launch(void* const* d_in, const int* in_sizes, int n_in,
                              void* d_out, int out_size)
{
    const float* x    = (const float*)d_in[0];  // [B, R, I]
    const float* W    = (const float*)d_in[1];  // [1, R, C, O, I]
    const float* bias = (const float*)d_in[2];  // [O, 1]
    float* out = (float*)d_out;                 // [B, R, C, O, 1]

    cudaFuncSetAttribute(digitcaps_kernel,
                         cudaFuncAttributeMaxDynamicSharedMemorySize, SMEM_BYTES);

    dim3 block(128, 1, 1);
    dim3 grid(DC_R / RB, DC_B / BT, 1);   // (288, 16)
    digitcaps_kernel<<<grid, block, SMEM_BYTES>>>(x, W, bias, out);
}

// round 9
// speedup vs baseline: 2.9717x; 2.9717x over previous
#include <cuda_runtime.h>

// DigitCaps broadcasted batched matvec:
//   u_hat[b,r,c,o] = sum_i W[r,c,o,i] * x[b,r,i] + bias[o]
// B=512, R=1152, C=10, O=16, I=8, fp32.
//
// R7: R5 structure (RB=4, BT=16, 128 threads, 7 CTAs/SM = 28 warps) with
// PLAIN stores. Cross-round evidence shows __stcs added ~20us of L1 time
// (L1 62% in R2/plain vs 84-89% in R3/R5/R6/__stcs, same store pattern).
// Output has no reuse to protect in L2, so evict-first bought nothing.
// Everything else identical to R5: padded conflict-free smem W rows,
// broadcast x LDS, 4-segment coalesced STG.128 stores (issue-cost floor).
// Lane = bg(4) x c2(2) x o4(4). Each thread: 4 b's (k) x 2 c's x 4 o's.

#define DC_B 512
#define DC_R 1152
#define DC_C 10
#define DC_O 16
#define DC_I 8

#define RB 4     // r rows per block (one per warp)
#define BT 16    // batch elems per block
// smem W: 4r * 10c * 4(o4) rows of 36 floats = 5760 floats (23KB)
// smem x: 16 b * 36 floats (32 data + 4 pad)  =  576 floats
#define SW_FLOATS 5760
#define SX_FLOATS 576
#define SMEM_BYTES ((SW_FLOATS + SX_FLOATS) * 4)

__global__ __launch_bounds__(128, 7)
void digitcaps_kernel(const float* __restrict__ x,
                      const float* __restrict__ W,
                      const float* __restrict__ bias,
                      float* __restrict__ out)
{
    extern __shared__ float smem[];
    float* sW = smem;                 // [g][36], g = (r_local*10 + c)*4 + o4
    float* sx = smem + SW_FLOATS;     // [b_local][36]: 4 r * 8 i + pad

    const int tid = threadIdx.x;
    const int r0  = blockIdx.x * RB;
    const int b0  = blockIdx.y * BT;

    // ---- cooperative W load: 4 r rows * 1280 floats = 1280 float4, coalesced ----
    {
        const float4* Wg = reinterpret_cast<const float4*>(W + (size_t)r0 * (DC_C * DC_O * DC_I));
#pragma unroll
        for (int q4 = 0; q4 < 10; ++q4) {
            const int q = q4 * 128 + tid;           // float4 index in W tile
            const float4 v = Wg[q];
            // q -> (rc, o, ih): flat = ((rc)*16 + o)*2 + ih
            const int ih = q & 1;
            const int o  = (q >> 1) & 15;
            const int rc = q >> 5;                   // r_local*10 + c
            const int g  = rc * 4 + (o >> 2);
            *reinterpret_cast<float4*>(sW + g * 36 + (o & 3) * 8 + ih * 4) = v;
        }
    }
    // ---- cooperative x load: 16 b * 32 floats = 128 float4 (one per thread),
    //      each b = exactly one 128B line of x ----
    {
        const int b_i = tid >> 3;                    // 0..15
        const int m   = tid & 7;                     // float4 index within line
        const float4 v = *reinterpret_cast<const float4*>(
            x + ((size_t)(b0 + b_i) * DC_R + r0) * DC_I + m * 4);
        *reinterpret_cast<float4*>(sx + b_i * 36 + m * 4) = v;
    }
    __syncthreads();

    const int lane = tid & 31;
    const int w    = tid >> 5;       // warp id == r_local (0..3)
    const int bg   = lane >> 3;      // 0..3 batch group
    const int c2   = (lane >> 2) & 1;
    const int o4   = lane & 3;

    const int r = r0 + w;

    const float4 bb = *reinterpret_cast<const float4*>(bias + o4 * 4);

    // out element offset: ((b*R + r)*C + c)*O + o
    const size_t out_r = (size_t)r * (DC_C * DC_O);

#pragma unroll
    for (int cp = 0; cp < 5; ++cp) {
        const int c = cp * 2 + c2;
        // W row for (r, c, o4): 32 floats = 4 o * 8 i. 8 distinct rows per warp,
        // row stride 36 floats -> conflict-free; 4-way bg broadcast dedups.
        const float* wr = sW + ((w * DC_C + c) * 4 + o4) * 36;
        const float4 w0a = *reinterpret_cast<const float4*>(wr + 0);
        const float4 w0b = *reinterpret_cast<const float4*>(wr + 4);
        const float4 w1a = *reinterpret_cast<const float4*>(wr + 8);
        const float4 w1b = *reinterpret_cast<const float4*>(wr + 12);
        const float4 w2a = *reinterpret_cast<const float4*>(wr + 16);
        const float4 w2b = *reinterpret_cast<const float4*>(wr + 20);
        const float4 w3a = *reinterpret_cast<const float4*>(wr + 24);
        const float4 w3b = *reinterpret_cast<const float4*>(wr + 28);

#pragma unroll
        for (int k = 0; k < 4; ++k) {
            const int bl = k * 4 + bg;
            // broadcast LDS: 4 distinct 16B addrs per warp instr
            const float4 va = *reinterpret_cast<const float4*>(sx + bl * 36 + w * 8);
            const float4 vb = *reinterpret_cast<const float4*>(sx + bl * 36 + w * 8 + 4);

            float4 acc;
            acc.x = fmaf(w0a.x, va.x, fmaf(w0a.y, va.y,
                    fmaf(w0a.z, va.z, fmaf(w0a.w, va.w,
                    fmaf(w0b.x, vb.x, fmaf(w0b.y, vb.y,
                    fmaf(w0b.z, vb.z, fmaf(w0b.w, vb.w, bb.x))))))));
            acc.y = fmaf(w1a.x, va.x, fmaf(w1a.y, va.y,
                    fmaf(w1a.z, va.z, fmaf(w1a.w, va.w,
                    fmaf(w1b.x, vb.x, fmaf(w1b.y, vb.y,
                    fmaf(w1b.z, vb.z, fmaf(w1b.w, vb.w, bb.y))))))));
            acc.z = fmaf(w2a.x, va.x, fmaf(w2a.y, va.y,
                    fmaf(w2a.z, va.z, fmaf(w2a.w, va.w,
                    fmaf(w2b.x, vb.x, fmaf(w2b.y, vb.y,
                    fmaf(w2b.z, vb.z, fmaf(w2b.w, vb.w, bb.z))))))));
            acc.w = fmaf(w3a.x, va.x, fmaf(w3a.y, va.y,
                    fmaf(w3a.z, va.z, fmaf(w3a.w, va.w,
                    fmaf(w3b.x, vb.x, fmaf(w3b.y, vb.y,
                    fmaf(w3b.z, vb.z, fmaf(w3b.w, vb.w, bb.w))))))));

            const int b = b0 + bl;
            // Per STG warp instr: 4 x 128B contiguous segments (plain store).
            float4* op = reinterpret_cast<float4*>(
                out + (size_t)b * (DC_R * DC_C * DC_O) + out_r
                    + (size_t)c * DC_O + o4 * 4);
            *op = acc;
        }
    }
}

extern "C" void kernel_launch(void* const* d_in, const int* in_sizes, int n_in,
                              void* d_out, int out_size)
{
    const float* x    = (const float*)d_in[0];  // [B, R, I]
    const float* W    = (const float*)d_in[1];  // [1, R, C, O, I]
    const float* bias = (const float*)d_in[2];  // [O, 1]
    float* out = (float*)d_out;                 // [B, R, C, O, 1]

    cudaFuncSetAttribute(digitcaps_kernel,
                         cudaFuncAttributeMaxDynamicSharedMemorySize, SMEM_BYTES);

    dim3 block(128, 1, 1);
    dim3 grid(DC_R / RB, DC_B / BT, 1);   // (288, 32)
    digitcaps_kernel<<<grid, block, SMEM_BYTES>>>(x, W, bias, out);
}

// round 10
// speedup vs baseline: 3.3942x; 1.1422x over previous
#include <cuda_runtime.h>

// DigitCaps broadcasted batched matvec:
//   u_hat[b,r,c,o] = sum_i W[r,c,o,i] * x[b,r,i] + bias[o]
// B=512, R=1152, C=10, O=16, I=8, fp32.
//
// R8: R2's per-thread profile (x held in registers via uniform-address
// LDG.128 -- all lanes in a warp share r, so each x load is a single-line
// broadcast; BT=16; identical FMA and 4-segment STG.128 store shape) at
// RB=4 / block=128 / 6 CTAs per SM (24 warps, vs R2's 16).
// Measured evidence: configs reading x from smem in the inner loop run L1 at
// 84-89%; configs with x-in-regs run 62-80%. Keep the cheap mix, add warps.
// Lane = bg(4) x c2(2) x o4(4). Each thread: 4 b's (k) x 2 c's x 4 o's,
// with x for all 16 block b's... (each thread holds its own 4 b-groups'
// slots via k*4+bg indexing, 8 float4 pairs total).

#define DC_B 512
#define DC_R 1152
#define DC_C 10
#define DC_O 16
#define DC_I 8

#define RB 4     // r rows per block (one per warp)
#define BT 16    // batch elems per block
// smem W: 4r * 10c * 4(o4) rows of 36 floats = 5760 floats (23KB)
#define SW_FLOATS 5760
#define SMEM_BYTES (SW_FLOATS * 4)

__global__ __launch_bounds__(128, 6)
void digitcaps_kernel(const float* __restrict__ x,
                      const float* __restrict__ W,
                      const float* __restrict__ bias,
                      float* __restrict__ out)
{
    extern __shared__ float smem[];
    float* sW = smem;                 // [g][36], g = (r_local*10 + c)*4 + o4

    const int tid = threadIdx.x;
    const int r0  = blockIdx.x * RB;
    const int b0  = blockIdx.y * BT;

    // ---- cooperative W load: 4 r rows * 1280 floats = 1280 float4, coalesced ----
    {
        const float4* Wg = reinterpret_cast<const float4*>(W + (size_t)r0 * (DC_C * DC_O * DC_I));
#pragma unroll
        for (int q4 = 0; q4 < 10; ++q4) {
            const int q = q4 * 128 + tid;           // float4 index in W tile
            const float4 v = Wg[q];
            // q -> (rc, o, ih): flat = ((rc)*16 + o)*2 + ih
            const int ih = q & 1;
            const int o  = (q >> 1) & 15;
            const int rc = q >> 5;                   // r_local*10 + c
            const int g  = rc * 4 + (o >> 2);
            *reinterpret_cast<float4*>(sW + g * 36 + (o & 3) * 8 + ih * 4) = v;
        }
    }

    const int lane = tid & 31;
    const int w    = tid >> 5;       // warp id == r_local (0..3)
    const int bg   = lane >> 3;      // 0..3 batch group
    const int c2   = (lane >> 2) & 1;
    const int o4   = lane & 3;

    const int r = r0 + w;

    // ---- x in registers: this thread's 4 b's (bl = k*4+bg), 8 floats each.
    //      Address depends only on (b, r) -> uniform across the 8 lanes that
    //      share bg; 4 distinct 32B runs per warp instr, L1-resident line. ----
    float4 xa[4], xb[4];
#pragma unroll
    for (int k = 0; k < 4; ++k) {
        const int bl = k * 4 + bg;
        const float4* xp = reinterpret_cast<const float4*>(
            x + ((size_t)(b0 + bl) * DC_R + r) * DC_I);
        xa[k] = xp[0];
        xb[k] = xp[1];
    }

    const float4 bb = *reinterpret_cast<const float4*>(bias + o4 * 4);

    __syncthreads();

    // out element offset: ((b*R + r)*C + c)*O + o
    const size_t out_r = (size_t)r * (DC_C * DC_O);

#pragma unroll
    for (int cp = 0; cp < 5; ++cp) {
        const int c = cp * 2 + c2;
        // W row for (r, c, o4): 32 floats = 4 o * 8 i. 8 distinct rows per warp,
        // row stride 36 floats -> conflict-free; 4-way bg broadcast dedups.
        const float* wr = sW + ((w * DC_C + c) * 4 + o4) * 36;
        const float4 w0a = *reinterpret_cast<const float4*>(wr + 0);
        const float4 w0b = *reinterpret_cast<const float4*>(wr + 4);
        const float4 w1a = *reinterpret_cast<const float4*>(wr + 8);
        const float4 w1b = *reinterpret_cast<const float4*>(wr + 12);
        const float4 w2a = *reinterpret_cast<const float4*>(wr + 16);
        const float4 w2b = *reinterpret_cast<const float4*>(wr + 20);
        const float4 w3a = *reinterpret_cast<const float4*>(wr + 24);
        const float4 w3b = *reinterpret_cast<const float4*>(wr + 28);

#pragma unroll
        for (int k = 0; k < 4; ++k) {
            const float4 va = xa[k];
            const float4 vb = xb[k];

            float4 acc;
            acc.x = fmaf(w0a.x, va.x, fmaf(w0a.y, va.y,
                    fmaf(w0a.z, va.z, fmaf(w0a.w, va.w,
                    fmaf(w0b.x, vb.x, fmaf(w0b.y, vb.y,
                    fmaf(w0b.z, vb.z, fmaf(w0b.w, vb.w, bb.x))))))));
            acc.y = fmaf(w1a.x, va.x, fmaf(w1a.y, va.y,
                    fmaf(w1a.z, va.z, fmaf(w1a.w, va.w,
                    fmaf(w1b.x, vb.x, fmaf(w1b.y, vb.y,
                    fmaf(w1b.z, vb.z, fmaf(w1b.w, vb.w, bb.y))))))));
            acc.z = fmaf(w2a.x, va.x, fmaf(w2a.y, va.y,
                    fmaf(w2a.z, va.z, fmaf(w2a.w, va.w,
                    fmaf(w2b.x, vb.x, fmaf(w2b.y, vb.y,
                    fmaf(w2b.z, vb.z, fmaf(w2b.w, vb.w, bb.z))))))));
            acc.w = fmaf(w3a.x, va.x, fmaf(w3a.y, va.y,
                    fmaf(w3a.z, va.z, fmaf(w3a.w, va.w,
                    fmaf(w3b.x, vb.x, fmaf(w3b.y, vb.y,
                    fmaf(w3b.z, vb.z, fmaf(w3b.w, vb.w, bb.w))))))));

            const int b = b0 + k * 4 + bg;
            // Per STG warp instr: 4 x 128B contiguous segments (plain store).
            float4* op = reinterpret_cast<float4*>(
                out + (size_t)b * (DC_R * DC_C * DC_O) + out_r
                    + (size_t)c * DC_O + o4 * 4);
            *op = acc;
        }
    }
}

extern "C" void kernel_launch(void* const* d_in, const int* in_sizes, int n_in,
                              void* d_out, int out_size)
{
    const float* x    = (const float*)d_in[0];  // [B, R, I]
    const float* W    = (const float*)d_in[1];  // [1, R, C, O, I]
    const float* bias = (const float*)d_in[2];  // [O, 1]
    float* out = (float*)d_out;                 // [B, R, C, O, 1]

    cudaFuncSetAttribute(digitcaps_kernel,
                         cudaFuncAttributeMaxDynamicSharedMemorySize, SMEM_BYTES);

    dim3 block(128, 1, 1);
    dim3 grid(DC_R / RB, DC_B / BT, 1);   // (288, 32)
    digitcaps_kernel<<<grid, block, SMEM_BYTES>>>(x, W, bias, out);
}